// round 3
// baseline (speedup 1.0000x reference)
#include <cuda_runtime.h>
#include <math.h>

#define N_NODES 50000
#define N_PAIRS 4096
#define N_EDGESC 500000
#define N_SP    1000000
#define FEAT 300
#define HID 128
#define HEADS 3
#define H1DIM 384
#define OUTC 10
#define ETOT (N_EDGESC + N_NODES)

// ------------------- scratch (device globals; no allocation) -------------------
__device__ float g_q[N_PAIRS * FEAT];
__device__ float g_k[N_PAIRS * FEAT];
__device__ float g_v[N_PAIRS * FEAT];
__device__ float g_S[(size_t)N_PAIRS * N_PAIRS];
__device__ float g_attn[N_PAIRS * FEAT];
__device__ float g_fused[N_PAIRS * FEAT];
__device__ float g_xw[(size_t)N_NODES * FEAT];
__device__ float g_h1[(size_t)N_NODES * H1DIM];
__device__ float g_out1[(size_t)N_NODES * H1DIM];
__device__ float g_h2[N_NODES * OUTC];
__device__ float g_emb[N_NODES * OUTC];
__device__ float g_es1[N_NODES * HEADS];
__device__ float g_ed1[N_NODES * HEADS];
__device__ float g_es2[N_NODES];
__device__ float g_ed2[N_NODES];
__device__ int   g_deg[N_NODES];
__device__ int   g_rowptr[N_NODES + 1];
__device__ int   g_cursor[N_NODES];
__device__ int   g_adj[ETOT];
__device__ int   g_winner[N_NODES];

__device__ __forceinline__ float lrelu(float x) { return x > 0.f ? x : 0.2f * x; }

// ------------------- SGEMM: C = A @ B (+bias)(+addm), optional B-transpose -----
// A: [M,K] row-major. TB=false: B [K,N]. TB=true: B [N,K] (C=A@B^T).
template <bool TB>
__global__ void sgemm_kernel(const float* __restrict__ A, const float* __restrict__ B,
                             const float* __restrict__ bias, const float* __restrict__ addm,
                             float* __restrict__ C, int M, int N, int K)
{
    const int BM = 64, BN = 64, BK = 16;
    __shared__ __align__(16) float As[BK][BM + 4];
    __shared__ __align__(16) float Bs[BK][BN + 4];
    int bm = blockIdx.y * BM, bn = blockIdx.x * BN;
    int tid = threadIdx.x;
    int tx = tid & 15, ty = tid >> 4;
    float acc[4][4] = {};

    for (int k0 = 0; k0 < K; k0 += BK) {
#pragma unroll
        for (int i = 0; i < 4; i++) {
            int idx = tid + 256 * i;
            int m = idx >> 4, kk = idx & 15;
            int gm = bm + m, gk = k0 + kk;
            As[kk][m] = (gm < M && gk < K) ? A[(size_t)gm * K + gk] : 0.f;
        }
        if (!TB) {
#pragma unroll
            for (int i = 0; i < 4; i++) {
                int idx = tid + 256 * i;
                int kk = idx >> 6, nn = idx & 63;
                int gk = k0 + kk, gn = bn + nn;
                Bs[kk][nn] = (gk < K && gn < N) ? B[(size_t)gk * N + gn] : 0.f;
            }
        } else {
#pragma unroll
            for (int i = 0; i < 4; i++) {
                int idx = tid + 256 * i;
                int nn = idx >> 4, kk = idx & 15;
                int gn = bn + nn, gk = k0 + kk;
                Bs[kk][nn] = (gn < N && gk < K) ? B[(size_t)gn * K + gk] : 0.f;
            }
        }
        __syncthreads();
#pragma unroll
        for (int kk = 0; kk < BK; kk++) {
            float4 av = *reinterpret_cast<const float4*>(&As[kk][ty * 4]);
            float4 bv = *reinterpret_cast<const float4*>(&Bs[kk][tx * 4]);
            float a[4] = {av.x, av.y, av.z, av.w};
            float b[4] = {bv.x, bv.y, bv.z, bv.w};
#pragma unroll
            for (int i = 0; i < 4; i++)
#pragma unroll
                for (int j = 0; j < 4; j++)
                    acc[i][j] += a[i] * b[j];
        }
        __syncthreads();
    }
#pragma unroll
    for (int i = 0; i < 4; i++) {
        int gm = bm + ty * 4 + i;
        if (gm >= M) continue;
#pragma unroll
        for (int j = 0; j < 4; j++) {
            int gn = bn + tx * 4 + j;
            if (gn >= N) continue;
            float vv = acc[i][j];
            if (bias) vv += bias[gn];
            if (addm) vv += addm[(size_t)gm * N + gn];
            C[(size_t)gm * N + gn] = vv;
        }
    }
}

// ------------------- row softmax of the 4096x4096 score matrix ---------------
__global__ void softmax4096(float* __restrict__ S)
{
    int row = blockIdx.x;
    float* r = S + (size_t)row * 4096;
    const float scale = 0.05773502691896258f; // 1/sqrt(300)
    float vals[16];
    float mx = -1e30f;
#pragma unroll
    for (int i = 0; i < 16; i++) {
        float v = r[threadIdx.x + 256 * i] * scale;
        vals[i] = v;
        mx = fmaxf(mx, v);
    }
    __shared__ float sh[8];
    for (int o = 16; o; o >>= 1) mx = fmaxf(mx, __shfl_xor_sync(0xffffffffu, mx, o));
    int w = threadIdx.x >> 5;
    if ((threadIdx.x & 31) == 0) sh[w] = mx;
    __syncthreads();
    mx = sh[0];
#pragma unroll
    for (int i = 1; i < 8; i++) mx = fmaxf(mx, sh[i]);
    __syncthreads();
    float se = 0.f;
#pragma unroll
    for (int i = 0; i < 16; i++) {
        vals[i] = expf(vals[i] - mx);
        se += vals[i];
    }
    for (int o = 16; o; o >>= 1) se += __shfl_xor_sync(0xffffffffu, se, o);
    if ((threadIdx.x & 31) == 0) sh[w] = se;
    __syncthreads();
    se = 0.f;
#pragma unroll
    for (int i = 0; i < 8; i++) se += sh[i];
    float inv = 1.f / se;
#pragma unroll
    for (int i = 0; i < 16; i++) r[threadIdx.x + 256 * i] = vals[i] * inv;
}

// ------------------- x_work = x; scatter fused rows (last-index-wins) --------
__global__ void copy_x_kernel(const float4* __restrict__ x)
{
    size_t t = (size_t)blockIdx.x * blockDim.x + threadIdx.x;
    if (t < (size_t)N_NODES * FEAT / 4) reinterpret_cast<float4*>(g_xw)[t] = x[t];
}

__global__ void winner_init_kernel()
{
    int n = blockIdx.x * blockDim.x + threadIdx.x;
    if (n < N_NODES) g_winner[n] = -1;
}

__global__ void winner_max_kernel(const int* __restrict__ cidx)
{
    int i = blockIdx.x * blockDim.x + threadIdx.x;
    if (i < N_PAIRS) atomicMax(&g_winner[cidx[i]], i);
}

__global__ void scatter_fused_kernel(const int* __restrict__ cidx)
{
    int t = blockIdx.x * blockDim.x + threadIdx.x;
    if (t < N_PAIRS * FEAT) {
        int i = t / FEAT, c = t - i * FEAT;
        int node = cidx[i];
        if (g_winner[node] == i) g_xw[(size_t)node * FEAT + c] = g_fused[t];
    }
}

// ------------------- CSR build (by dst, includes self-loops) -----------------
__global__ void deg_init_kernel()
{
    int n = blockIdx.x * blockDim.x + threadIdx.x;
    if (n < N_NODES) g_deg[n] = 1;  // self-loop
}

__global__ void deg_count_kernel(const int* __restrict__ dst)
{
    int e = blockIdx.x * blockDim.x + threadIdx.x;
    if (e < N_EDGESC) atomicAdd(&g_deg[dst[e]], 1);
}

__global__ void exscan_kernel()
{
    __shared__ int wsum[32];
    __shared__ int carry;
    if (threadIdx.x == 0) carry = 0;
    int lane = threadIdx.x & 31, wid = threadIdx.x >> 5;
    __syncthreads();
    for (int base = 0; base < N_NODES; base += 1024) {
        int i = base + threadIdx.x;
        int v = (i < N_NODES) ? g_deg[i] : 0;
        int x = v;
        for (int o = 1; o < 32; o <<= 1) {
            int t = __shfl_up_sync(0xffffffffu, x, o);
            if (lane >= o) x += t;
        }
        if (lane == 31) wsum[wid] = x;
        __syncthreads();
        if (wid == 0) {
            int y = wsum[lane];
            for (int o = 1; o < 32; o <<= 1) {
                int t = __shfl_up_sync(0xffffffffu, y, o);
                if (lane >= o) y += t;
            }
            wsum[lane] = y;
        }
        __syncthreads();
        int incl = x + (wid ? wsum[wid - 1] : 0);
        int c = carry;
        if (i < N_NODES) g_rowptr[i + 1] = c + incl;
        __syncthreads();
        if (threadIdx.x == 1023) carry = c + incl;
        __syncthreads();
    }
    if (threadIdx.x == 0) g_rowptr[0] = 0;
}

__global__ void cursor_copy_kernel()
{
    int n = blockIdx.x * blockDim.x + threadIdx.x;
    if (n < N_NODES) g_cursor[n] = g_rowptr[n];
}

__global__ void fill_edges_kernel(const int* __restrict__ src, const int* __restrict__ dst)
{
    int e = blockIdx.x * blockDim.x + threadIdx.x;
    if (e < N_EDGESC) {
        int d = dst[e];
        int p = atomicAdd(&g_cursor[d], 1);
        g_adj[p] = src[e];
    }
}

__global__ void fill_self_kernel()
{
    int n = blockIdx.x * blockDim.x + threadIdx.x;
    if (n < N_NODES) {
        int p = atomicAdd(&g_cursor[n], 1);
        g_adj[p] = n;
    }
}

// ------------------- attention coefficients ----------------------------------
__global__ void e1_kernel(const float* __restrict__ asrc, const float* __restrict__ adst)
{
    int n = blockIdx.x;
    int w = threadIdx.x >> 5, lane = threadIdx.x & 31;
    if (w >= HEADS) return;
    const float* hrow = g_h1 + (size_t)n * H1DIM + w * HID;
    float s = 0.f, d = 0.f;
    for (int c = lane; c < HID; c += 32) {
        float hv = hrow[c];
        s += hv * asrc[w * HID + c];
        d += hv * adst[w * HID + c];
    }
    for (int o = 16; o; o >>= 1) {
        s += __shfl_xor_sync(0xffffffffu, s, o);
        d += __shfl_xor_sync(0xffffffffu, d, o);
    }
    if (lane == 0) {
        g_es1[n * HEADS + w] = s;
        g_ed1[n * HEADS + w] = d;
    }
}

__global__ void e2_kernel(const float* __restrict__ asrc, const float* __restrict__ adst)
{
    int n = blockIdx.x * blockDim.x + threadIdx.x;
    if (n >= N_NODES) return;
    const float* r = g_h2 + (size_t)n * OUTC;
    float s = 0.f, d = 0.f;
#pragma unroll
    for (int c = 0; c < OUTC; c++) {
        s += r[c] * asrc[c];
        d += r[c] * adst[c];
    }
    g_es2[n] = s;
    g_ed2[n] = d;
}

// ------------------- GAT layer-1 aggregation (warp per node) + bias + ELU ----
__global__ void gat_agg1_kernel(const float* __restrict__ b1)
{
    int n = blockIdx.x * (blockDim.x >> 5) + (threadIdx.x >> 5);
    int lane = threadIdx.x & 31;
    if (n >= N_NODES) return;
    int s = g_rowptr[n], e = g_rowptr[n + 1];
    float ed0 = g_ed1[n * 3 + 0], ed1 = g_ed1[n * 3 + 1], ed2 = g_ed1[n * 3 + 2];

    float m0 = -1e30f, m1 = -1e30f, m2 = -1e30f;
    for (int j = s + lane; j < e; j += 32) {
        int sj = g_adj[j];
        m0 = fmaxf(m0, lrelu(g_es1[sj * 3 + 0] + ed0));
        m1 = fmaxf(m1, lrelu(g_es1[sj * 3 + 1] + ed1));
        m2 = fmaxf(m2, lrelu(g_es1[sj * 3 + 2] + ed2));
    }
    for (int o = 16; o; o >>= 1) {
        m0 = fmaxf(m0, __shfl_xor_sync(0xffffffffu, m0, o));
        m1 = fmaxf(m1, __shfl_xor_sync(0xffffffffu, m1, o));
        m2 = fmaxf(m2, __shfl_xor_sync(0xffffffffu, m2, o));
    }
    float d0 = 0.f, d1 = 0.f, d2 = 0.f;
    for (int j = s + lane; j < e; j += 32) {
        int sj = g_adj[j];
        d0 += expf(lrelu(g_es1[sj * 3 + 0] + ed0) - m0);
        d1 += expf(lrelu(g_es1[sj * 3 + 1] + ed1) - m1);
        d2 += expf(lrelu(g_es1[sj * 3 + 2] + ed2) - m2);
    }
    for (int o = 16; o; o >>= 1) {
        d0 += __shfl_xor_sync(0xffffffffu, d0, o);
        d1 += __shfl_xor_sync(0xffffffffu, d1, o);
        d2 += __shfl_xor_sync(0xffffffffu, d2, o);
    }
    d0 += 1e-16f; d1 += 1e-16f; d2 += 1e-16f;

    float acc[12] = {};
    for (int j = s; j < e; j++) {
        int sj = g_adj[j];
        float a0 = expf(lrelu(g_es1[sj * 3 + 0] + ed0) - m0) / d0;
        float a1 = expf(lrelu(g_es1[sj * 3 + 1] + ed1) - m1) / d1;
        float a2 = expf(lrelu(g_es1[sj * 3 + 2] + ed2) - m2) / d2;
        const float* row = g_h1 + (size_t)sj * H1DIM;
#pragma unroll
        for (int t = 0; t < 4; t++) acc[t] += a0 * row[lane + 32 * t];
#pragma unroll
        for (int t = 4; t < 8; t++) acc[t] += a1 * row[lane + 32 * t];
#pragma unroll
        for (int t = 8; t < 12; t++) acc[t] += a2 * row[lane + 32 * t];
    }
    float* o = g_out1 + (size_t)n * H1DIM;
#pragma unroll
    for (int t = 0; t < 12; t++) {
        int c = lane + 32 * t;
        float vv = acc[t] + b1[c];
        o[c] = vv > 0.f ? vv : expm1f(vv);  // fused ELU
    }
}

// ------------------- GAT layer-2 aggregation (warp per node) + bias ----------
__global__ void gat_agg2_kernel(const float* __restrict__ b2)
{
    int n = blockIdx.x * (blockDim.x >> 5) + (threadIdx.x >> 5);
    int lane = threadIdx.x & 31;
    if (n >= N_NODES) return;
    int s = g_rowptr[n], e = g_rowptr[n + 1];
    float ed = g_ed2[n];

    float m = -1e30f;
    for (int j = s + lane; j < e; j += 32) m = fmaxf(m, lrelu(g_es2[g_adj[j]] + ed));
    for (int o = 16; o; o >>= 1) m = fmaxf(m, __shfl_xor_sync(0xffffffffu, m, o));
    float den = 0.f;
    for (int j = s + lane; j < e; j += 32) den += expf(lrelu(g_es2[g_adj[j]] + ed) - m);
    for (int o = 16; o; o >>= 1) den += __shfl_xor_sync(0xffffffffu, den, o);
    den += 1e-16f;

    float acc[OUTC] = {};
    for (int j = s + lane; j < e; j += 32) {
        int sj = g_adj[j];
        float al = expf(lrelu(g_es2[sj] + ed) - m) / den;
        const float* r = g_h2 + (size_t)sj * OUTC;
#pragma unroll
        for (int c = 0; c < OUTC; c++) acc[c] += al * r[c];
    }
#pragma unroll
    for (int c = 0; c < OUTC; c++)
        for (int o = 16; o; o >>= 1) acc[c] += __shfl_xor_sync(0xffffffffu, acc[c], o);
    if (lane == 0) {
#pragma unroll
        for (int c = 0; c < OUTC; c++) g_emb[(size_t)n * OUTC + c] = acc[c] + b2[c];
    }
}

// ------------------- pair scoring --------------------------------------------
__global__ void score_kernel(const int* __restrict__ pair, float* __restrict__ out)
{
    int p = blockIdx.x * blockDim.x + threadIdx.x;
    if (p >= N_SP) return;
    const float* a = g_emb + (size_t)pair[2 * p] * OUTC;
    const float* b = g_emb + (size_t)pair[2 * p + 1] * OUTC;
    float s = 0.f;
#pragma unroll
    for (int c = 0; c < OUTC; c++) s += a[c] * b[c];
    out[p] = s;
}

// ------------------- host orchestration --------------------------------------
extern "C" void kernel_launch(void* const* d_in, const int* in_sizes, int n_in,
                              void* d_out, int out_size)
{
    const float* f_sub  = (const float*)d_in[0];
    const float* f_com  = (const float*)d_in[1];
    const float* x      = (const float*)d_in[2];
    const int*   com_ix = (const int*)d_in[3];
    const int*   eidx   = (const int*)d_in[4];
    const int*   pair   = (const int*)d_in[5];
    const float* Wq = (const float*)d_in[6],  *bq = (const float*)d_in[7];
    const float* Wk = (const float*)d_in[8],  *bk = (const float*)d_in[9];
    const float* Wv = (const float*)d_in[10], *bv = (const float*)d_in[11];
    const float* Wf = (const float*)d_in[12], *bf = (const float*)d_in[13];
    const float* W1 = (const float*)d_in[14];
    const float* as1 = (const float*)d_in[15], *ad1 = (const float*)d_in[16];
    const float* b1 = (const float*)d_in[17];
    const float* W2 = (const float*)d_in[18];
    const float* as2 = (const float*)d_in[19], *ad2 = (const float*)d_in[20];
    const float* b2 = (const float*)d_in[21];
    float* out = (float*)d_out;

    const int* src = eidx;
    const int* dst = eidx + N_EDGESC;

    float *qp, *kp, *vp, *Sp, *attnp, *fusedp, *xwp, *h1p, *out1p, *h2p;
    cudaGetSymbolAddress((void**)&qp, g_q);
    cudaGetSymbolAddress((void**)&kp, g_k);
    cudaGetSymbolAddress((void**)&vp, g_v);
    cudaGetSymbolAddress((void**)&Sp, g_S);
    cudaGetSymbolAddress((void**)&attnp, g_attn);
    cudaGetSymbolAddress((void**)&fusedp, g_fused);
    cudaGetSymbolAddress((void**)&xwp, g_xw);
    cudaGetSymbolAddress((void**)&h1p, g_h1);
    cudaGetSymbolAddress((void**)&out1p, g_out1);
    cudaGetSymbolAddress((void**)&h2p, g_h2);

    auto gemmNN = [&](const float* A, const float* B, const float* bias, const float* add,
                      float* C, int M, int N, int K) {
        dim3 grid((N + 63) / 64, (M + 63) / 64);
        sgemm_kernel<false><<<grid, 256>>>(A, B, bias, add, C, M, N, K);
    };

    // --- cross attention ---
    gemmNN(f_sub, Wq, bq, nullptr, qp, N_PAIRS, FEAT, FEAT);
    gemmNN(f_com, Wk, bk, nullptr, kp, N_PAIRS, FEAT, FEAT);
    gemmNN(f_com, Wv, bv, nullptr, vp, N_PAIRS, FEAT, FEAT);
    {
        dim3 grid(64, 64);
        sgemm_kernel<true><<<grid, 256>>>(qp, kp, nullptr, nullptr, Sp, N_PAIRS, N_PAIRS, FEAT);
    }
    softmax4096<<<N_PAIRS, 256>>>(Sp);
    gemmNN(Sp, vp, nullptr, f_sub, attnp, N_PAIRS, FEAT, N_PAIRS);
    gemmNN(attnp, Wf, bf, nullptr, fusedp, N_PAIRS, FEAT, FEAT);

    // --- scatter fused rows into node features (last-index-wins) ---
    copy_x_kernel<<<(N_NODES * FEAT / 4 + 255) / 256, 256>>>((const float4*)x);
    winner_init_kernel<<<(N_NODES + 255) / 256, 256>>>();
    winner_max_kernel<<<(N_PAIRS + 255) / 256, 256>>>(com_ix);
    scatter_fused_kernel<<<(N_PAIRS * FEAT + 255) / 256, 256>>>(com_ix);

    // --- CSR by dst (with self-loops) ---
    deg_init_kernel<<<(N_NODES + 255) / 256, 256>>>();
    deg_count_kernel<<<(N_EDGESC + 255) / 256, 256>>>(dst);
    exscan_kernel<<<1, 1024>>>();
    cursor_copy_kernel<<<(N_NODES + 255) / 256, 256>>>();
    fill_edges_kernel<<<(N_EDGESC + 255) / 256, 256>>>(src, dst);
    fill_self_kernel<<<(N_NODES + 255) / 256, 256>>>();

    // --- GAT layer 1 ---
    gemmNN(xwp, W1, nullptr, nullptr, h1p, N_NODES, H1DIM, FEAT);
    e1_kernel<<<N_NODES, 128>>>(as1, ad1);
    gat_agg1_kernel<<<(N_NODES + 3) / 4, 128>>>(b1);

    // --- GAT layer 2 ---
    gemmNN(out1p, W2, nullptr, nullptr, h2p, N_NODES, OUTC, H1DIM);
    e2_kernel<<<(N_NODES + 255) / 256, 256>>>(as2, ad2);
    gat_agg2_kernel<<<(N_NODES + 3) / 4, 128>>>(b2);

    // --- pair scores ---
    score_kernel<<<(N_SP + 255) / 256, 256>>>(pair, out);
}